// round 14
// baseline (speedup 1.0000x reference)
#include <cuda_runtime.h>
#include <cuda_bf16.h>

#define BATCH    16
#define TDIM     1024
#define DDIM     1024
#define RADIUS   15
#define NBLOCKS  1024
#define ROW_TOTAL (64 * BATCH * 5)
#define TAU0     2.2f
#define FULLM    0xFFFFFFFFu

typedef unsigned long long ull;

__device__ int g_counts[BATCH * DDIM];
__device__ int g_done;

__device__ __forceinline__ unsigned sortable(float f) {
    unsigned u = __float_as_uint(f);
    return u ^ (((unsigned)((int)u >> 31)) | 0x80000000u);
}
__device__ __forceinline__ float unsortable(unsigned s) {
    unsigned u = (s & 0x80000000u) ? (s ^ 0x80000000u) : ~s;
    return __uint_as_float(u);
}
__device__ __forceinline__ float comp4(float4 v, int j) {
    return (j == 0) ? v.x : (j == 1) ? v.y : (j == 2) ? v.z : v.w;
}

// cert + candidate walk + exact top-5 extraction + histogram atomics.
// src: the row's 1024 floats (global or smem mirror — identical indexing).
// m:   per-lane 32-bit element mask at threshold TAU0 (bit b=4c+j -> idx 128c+4lane+j).
__device__ __forceinline__ void select_row(unsigned m, const float* src,
                                           int lane, int g) {
    float tauf = TAU0;

    // Certificate: >=5 lanes hold a candidate => >=5 elements >= TAU0 => v5 >= TAU0.
    unsigned hasc = __ballot_sync(FULLM, m != 0);
    if (__builtin_expect(__popc(hasc) < 5, 0)) {
        // Cold exact fallback: knockout tau from reloads, re-mask.
        float lmax = __int_as_float(0xFF800000);
#pragma unroll
        for (int c = 0; c < 8; c++) {
            const float4 q = *(const float4*)(src + 128 * c + 4 * lane);
            lmax = fmaxf(lmax, fmaxf(fmaxf(q.x, q.y), fmaxf(q.z, q.w)));
        }
        unsigned s = sortable(lmax);
        unsigned tau_s = 0;
#pragma unroll
        for (int r = 0; r < 5; r++) {
            unsigned best = __reduce_max_sync(FULLM, s);
            tau_s = best;
            if (s == best) s = 0;   // drop ties: tau only shrinks (still a valid bound)
        }
        tauf = unsortable(tau_s);
        m = 0;
#pragma unroll
        for (int c = 0; c < 8; c++) {
            const float4 q = *(const float4*)(src + 128 * c + 4 * lane);
#pragma unroll
            for (int j = 0; j < 4; j++) {
                if (comp4(q, j) >= tauf) m |= 1u << (c * 4 + j);
            }
        }
    }
    int cnt = __popc(m);

    // Phase C: per-lane best key via bit walk.
    // key = (sortable(value) << 10) | (1023 - idx): value-major, lowest-index-wins.
    ull ck = 0;
    {
        unsigned mm = m;
        while (mm) {
            int b = __ffs(mm) - 1;
            mm &= mm - 1;
            int idx = 4 * lane + ((b >> 2) << 7) + (b & 3);
            float f = src[idx];
            ull key = ((ull)sortable(f) << 10) | (unsigned)(1023 - idx);
            if (key > ck) ck = key;
        }
    }

    // Phase D: exact top-5 extraction (value, lowest-index tie-break).
#pragma unroll
    for (int r = 0; r < 5; r++) {
        unsigned hi = (unsigned)(ck >> 10);
        unsigned bestv = __reduce_max_sync(FULLM, hi);
        unsigned myinv = (unsigned)(ck & 1023u);
        unsigned inv_c = (hi == bestv) ? myinv : 0u;
        unsigned besti = __reduce_max_sync(FULLM, inv_c);
        if (lane == r) {
            atomicAdd(&g_counts[g * DDIM + (1023 - (int)besti)], 1);
        }
        if (hi == bestv && myinv == besti) {          // unique winner lane
            cnt--;
            ull ub = ck;
            ull nk = 0;
            if (cnt > 0) {                             // rescan own bits for next-best
                unsigned mm = m;
                while (mm) {
                    int b = __ffs(mm) - 1;
                    mm &= mm - 1;
                    int idx = 4 * lane + ((b >> 2) << 7) + (b & 3);
                    float f = src[idx];
                    ull key = ((ull)sortable(f) << 10) | (unsigned)(1023 - idx);
                    if (key < ub && key > nk) nk = key;
                }
            }
            ck = nk;
        }
    }
}

// Two rows per warp, software-pipelined: row0 via LDG (registers), row1 staged
// into smem with cp.async (zero dest regs) and consumed after row0's select.
// Rows w and w+8192 share the same g (same timestep, batches 0-7 vs 8-15).
// Fused conv epilogue + monotone poll-sum barrier (no gpu-scope fences).
__global__ void __launch_bounds__(256, 6) fused_kernel(const float* __restrict__ in,
                                                       float* __restrict__ out) {
    __shared__ float stage[8][1024];     // 4KB per warp: row1 mirror
    __shared__ int wsum[8];
    __shared__ int s_sum;
    __shared__ int s_ticket;

    int wib = threadIdx.x >> 5;                          // warp in block [0,8)
    int lane = threadIdx.x & 31;
    int warpId = blockIdx.x * 8 + wib;                   // [0, 8192)
    int g = (warpId & (TDIM - 1)) >> 6;

    const float* row0 = in + (size_t)warpId * DDIM;
    const float* row1 = in + (size_t)(warpId + 8192) * DDIM;
    float* slice = stage[wib];

    // ---- Row0: 8 LDG.128 + elementwise mask ----
    unsigned m0 = 0;
    {
        float4 q[8];
        const float4* p = (const float4*)row0 + lane;
#pragma unroll
        for (int c = 0; c < 8; c++) q[c] = p[c * 32];
#pragma unroll
        for (int c = 0; c < 8; c++) {
#pragma unroll
            for (int j = 0; j < 4; j++) {
                if (comp4(q[c], j) >= TAU0) m0 |= 1u << (c * 4 + j);
            }
        }
    }

    // ---- Prefetch row1 into smem (no dest registers; flies during row0 select) ----
    {
        unsigned dst = (unsigned)__cvta_generic_to_shared(slice + 4 * lane);
        const float* src = row1 + 4 * lane;
#pragma unroll
        for (int c = 0; c < 8; c++) {
            asm volatile("cp.async.cg.shared.global [%0], [%1], 16;"
                         :: "r"(dst + 512 * c), "l"(src + 128 * c));
        }
        asm volatile("cp.async.commit_group;");
    }

    // ---- Row0 select (cert + C + D + atomics) overlaps row1 transfer ----
    select_row(m0, row0, lane, g);

    // ---- Row1: wait (should be complete), mask from smem, select ----
    asm volatile("cp.async.wait_group 0;");
    unsigned m1 = 0;
    {
        const float4* ps = (const float4*)(slice + 4 * lane);
#pragma unroll
        for (int c = 0; c < 8; c++) {
            float4 q = ps[c * 32];
#pragma unroll
            for (int j = 0; j < 4; j++) {
                if (comp4(q, j) >= TAU0) m1 |= 1u << (c * 4 + j);
            }
        }
    }
    select_row(m1, slice, lane, g);

    // ================= epilogue: last 16 ticket-takers run the conv =================
    __syncthreads();
    if (threadIdx.x == 0) s_ticket = atomicAdd(&g_done, 1);
    __syncthreads();
    int ticket = s_ticket;
    if (ticket < NBLOCKS - BATCH) return;

    if (ticket == NBLOCKS - 1 && threadIdx.x == 0) g_done = 0;  // all increments applied
    int crow = ticket - (NBLOCKS - BATCH);
    int tid = threadIdx.x;

    // Reuse the stage buffer for the conv row (all warps are past their smem use).
    float* srow = &stage[0][0];                 // needs 1024 + 2*RADIUS floats
    float* w = &stage[2][0];                    // weights (disjoint region)

    if (tid < 2 * RADIUS + 1) {
        int k = tid - RADIUS;
        w[tid] = 0.19947114020071635f * expf(-0.125f * (float)(k * k));
    }
    if (tid < RADIUS) { srow[tid] = 0.0f; srow[DDIM + RADIUS + tid] = 0.0f; }
    __syncthreads();   // stage reuse + weights visible

    // Poll-sum barrier: monotone counts + total match == consistent final snapshot.
    const int4* rowp = (const int4*)(g_counts + crow * DDIM);
    while (true) {
        int4 c4 = __ldcg(rowp + tid);                   // L2-coherent, bypass L1
        srow[RADIUS + tid * 4 + 0] = (float)c4.x;
        srow[RADIUS + tid * 4 + 1] = (float)c4.y;
        srow[RADIUS + tid * 4 + 2] = (float)c4.z;
        srow[RADIUS + tid * 4 + 3] = (float)c4.w;
        int part = c4.x + c4.y + c4.z + c4.w;
#pragma unroll
        for (int off = 16; off; off >>= 1) part += __shfl_xor_sync(FULLM, part, off);
        if ((tid & 31) == 0) wsum[tid >> 5] = part;
        __syncthreads();
        if (tid == 0) {
            int t = 0;
#pragma unroll
            for (int i = 0; i < 8; i++) t += wsum[i];
            s_sum = t;
        }
        __syncthreads();
        if (s_sum == ROW_TOTAL) break;
        __nanosleep(100);
    }

    ((int4*)(g_counts + crow * DDIM))[tid] = make_int4(0, 0, 0, 0);

    float4 acc;
#pragma unroll
    for (int i = 0; i < 4; i++) {
        int d = tid * 4 + i;
        float a = 0.0f;
#pragma unroll
        for (int k = 0; k < 2 * RADIUS + 1; k++) a += srow[d + k] * w[k];
        ((float*)&acc)[i] = a;
    }
    ((float4*)(out + crow * DDIM))[tid] = acc;
}

extern "C" void kernel_launch(void* const* d_in, const int* in_sizes, int n_in,
                              void* d_out, int out_size) {
    const float* in = (const float*)d_in[0];
    float* out = (float*)d_out;
    fused_kernel<<<NBLOCKS, 256>>>(in, out);
}

// round 15
// speedup vs baseline: 1.1194x; 1.1194x over previous
#include <cuda_runtime.h>
#include <cuda_bf16.h>

#define BATCH    16
#define TDIM     1024
#define DDIM     1024
#define RADIUS   15
#define NBLOCKS  4096
#define ROW_TOTAL (64 * BATCH * 5)
#define TAU0     2.2f

typedef unsigned long long ull;

__device__ int g_counts[BATCH * DDIM];
__device__ int g_done;

__device__ __forceinline__ unsigned sortable(float f) {
    unsigned u = __float_as_uint(f);
    return u ^ (((unsigned)((int)u >> 31)) | 0x80000000u);
}
__device__ __forceinline__ float unsortable(unsigned s) {
    unsigned u = (s & 0x80000000u) ? (s ^ 0x80000000u) : ~s;
    return __uint_as_float(u);
}
__device__ __forceinline__ float comp4(float4 v, int j) {
    return (j == 0) ? v.x : (j == 1) ? v.y : (j == 2) ? v.z : v.w;
}

// R11 measured-best body, repackaged in 128-thread blocks (grid 4096) to
// decorrelate per-SM warp phases via finer CTA churn. One warp per row,
// 32 elems/lane, 8 LDG.128 (MLP=8), branchless elementwise candidate mask,
// bit-driven extraction with L1-hot scalar reloads, exact top-5.
// Certificate: >=5 lanes hold a candidate => >=5 elements >= TAU0 => v5 >= TAU0.
// Cold exact knockout fallback otherwise. Fused conv epilogue + monotone
// poll-sum barrier (no gpu-scope fences: CCTL.IVALL flushes L1 chip-wide).
__global__ void __launch_bounds__(128, 12) fused_kernel(const float* __restrict__ in,
                                                        float* __restrict__ out) {
    const unsigned FULL = 0xFFFFFFFFu;
    int warp = (blockIdx.x * 128 + threadIdx.x) >> 5;   // row id [0, 16384)
    int lane = threadIdx.x & 31;
    int g = (warp & (TDIM - 1)) >> 6;

    const float* rowbase = in + (size_t)warp * DDIM;
    const float4* p = (const float4*)rowbase + lane;

    // ---- Pass 1: 8 independent LDG.128, branchless candidate mask ----
    // element index for bit b (=4c+j): 4*lane + 128*(b>>2) + (b&3)
    unsigned m = 0;
    {
        float4 q[8];
#pragma unroll
        for (int c = 0; c < 8; c++) q[c] = p[c * 32];
#pragma unroll
        for (int c = 0; c < 8; c++) {
#pragma unroll
            for (int j = 0; j < 4; j++) {
                if (comp4(q[c], j) >= TAU0) m |= 1u << (c * 4 + j);
            }
        }
    }

    // ---- Certificate: >=5 lanes with candidates => v5 >= TAU0 ----
    unsigned hasc = __ballot_sync(FULL, m != 0);
    if (__builtin_expect(__popc(hasc) < 5, 0)) {
        // ---- Cold exact fallback: knockout tau from L1 reloads, re-mask ----
        float4 q[8];
#pragma unroll
        for (int c = 0; c < 8; c++) q[c] = p[c * 32];
        float lmax = __int_as_float(0xFF800000);
#pragma unroll
        for (int c = 0; c < 8; c++)
            lmax = fmaxf(lmax, fmaxf(fmaxf(q[c].x, q[c].y), fmaxf(q[c].z, q[c].w)));
        unsigned s = sortable(lmax);
        unsigned tau_s = 0;
#pragma unroll
        for (int r = 0; r < 5; r++) {
            unsigned best = __reduce_max_sync(FULL, s);
            tau_s = best;
            if (s == best) s = 0;   // drop ties: tau only shrinks (still a valid bound)
        }
        float tauf = unsortable(tau_s);
        m = 0;
#pragma unroll
        for (int c = 0; c < 8; c++) {
#pragma unroll
            for (int j = 0; j < 4; j++) {
                if (comp4(q[c], j) >= tauf) m |= 1u << (c * 4 + j);
            }
        }
    }
    int cnt = __popc(m);   // this lane's candidate count

    // ---- Phase C: per-lane best key via bit walk (E[bits] = 0.44/lane) ----
    // key = (sortable(value) << 10) | (1023 - idx): value-major, lowest-index-wins.
    ull ck = 0;
    {
        unsigned mm = m;
        while (mm) {
            int b = __ffs(mm) - 1;
            mm &= mm - 1;
            int idx = 4 * lane + ((b >> 2) << 7) + (b & 3);
            float f = rowbase[idx];                     // L1-hot scalar reload
            ull key = ((ull)sortable(f) << 10) | (unsigned)(1023 - idx);
            if (key > ck) ck = key;
        }
    }

    // ---- Phase D: exact top-5 extraction (value, lowest-index tie-break) ----
    int myidx = 0;
#pragma unroll
    for (int r = 0; r < 5; r++) {
        unsigned hi = (unsigned)(ck >> 10);
        unsigned bestv = __reduce_max_sync(FULL, hi);
        unsigned myinv = (unsigned)(ck & 1023u);
        unsigned inv_c = (hi == bestv) ? myinv : 0u;
        unsigned besti = __reduce_max_sync(FULL, inv_c);
        if (lane == r) myidx = 1023 - (int)besti;
        if (hi == bestv && myinv == besti) {            // unique winner lane
            cnt--;
            ull ub = ck;
            ull nk = 0;
            if (cnt > 0) {                               // rescan own bits for next-best
                unsigned mm = m;
                while (mm) {
                    int b = __ffs(mm) - 1;
                    mm &= mm - 1;
                    int idx = 4 * lane + ((b >> 2) << 7) + (b & 3);
                    float f = rowbase[idx];
                    ull key = ((ull)sortable(f) << 10) | (unsigned)(1023 - idx);
                    if (key < ub && key > nk) nk = key;
                }
            }
            ck = nk;
        }
    }

    if (lane < 5) atomicAdd(&g_counts[g * DDIM + myidx], 1);

    // ================= epilogue: last 16 ticket-takers run the conv =================
    __shared__ int s_ticket;
    __syncthreads();
    if (threadIdx.x == 0) s_ticket = atomicAdd(&g_done, 1);
    __syncthreads();
    int ticket = s_ticket;
    if (ticket < NBLOCKS - BATCH) return;

    if (ticket == NBLOCKS - 1 && threadIdx.x == 0) g_done = 0;  // all increments applied
    int crow = ticket - (NBLOCKS - BATCH);
    int tid = threadIdx.x;   // [0, 128)

    __shared__ float srow[DDIM + 2 * RADIUS];
    __shared__ float w[2 * RADIUS + 1];
    __shared__ int wsum[4];
    __shared__ int s_sum;

    if (tid < 2 * RADIUS + 1) {
        int k = tid - RADIUS;
        w[tid] = 0.19947114020071635f * expf(-0.125f * (float)(k * k));
    }
    if (tid < RADIUS) { srow[tid] = 0.0f; srow[DDIM + RADIUS + tid] = 0.0f; }

    // Poll-sum barrier: monotone counts + total match == consistent final snapshot.
    const int4* rowp = (const int4*)(g_counts + crow * DDIM);   // 256 int4
    while (true) {
        int part = 0;
#pragma unroll
        for (int h = 0; h < 2; h++) {
            int4 c4 = __ldcg(rowp + tid * 2 + h);       // L2-coherent, bypass L1
            int base = RADIUS + tid * 8 + h * 4;
            srow[base + 0] = (float)c4.x;
            srow[base + 1] = (float)c4.y;
            srow[base + 2] = (float)c4.z;
            srow[base + 3] = (float)c4.w;
            part += c4.x + c4.y + c4.z + c4.w;
        }
#pragma unroll
        for (int off = 16; off; off >>= 1) part += __shfl_xor_sync(FULL, part, off);
        if ((tid & 31) == 0) wsum[tid >> 5] = part;
        __syncthreads();
        if (tid == 0) s_sum = wsum[0] + wsum[1] + wsum[2] + wsum[3];
        __syncthreads();
        if (s_sum == ROW_TOTAL) break;
        __nanosleep(100);
    }

    // Restore invariant for the next replay (all reads complete block-wide).
#pragma unroll
    for (int h = 0; h < 2; h++)
        ((int4*)(g_counts + crow * DDIM))[tid * 2 + h] = make_int4(0, 0, 0, 0);

    // conv: out[crow][d] = sum_k srow[d+k] * w[k]; 8 outputs per thread.
#pragma unroll
    for (int h = 0; h < 2; h++) {
        float4 acc;
#pragma unroll
        for (int i = 0; i < 4; i++) {
            int d = tid * 8 + h * 4 + i;
            float a = 0.0f;
#pragma unroll
            for (int k = 0; k < 2 * RADIUS + 1; k++) a += srow[d + k] * w[k];
            ((float*)&acc)[i] = a;
        }
        ((float4*)(out + crow * DDIM))[tid * 2 + h] = acc;
    }
}

extern "C" void kernel_launch(void* const* d_in, const int* in_sizes, int n_in,
                              void* d_out, int out_size) {
    const float* in = (const float*)d_in[0];
    float* out = (float*)d_out;
    fused_kernel<<<NBLOCKS, 128>>>(in, out);
}